// round 2
// baseline (speedup 1.0000x reference)
#include <cuda_runtime.h>
#include <math.h>

#define NN 50000
#define NE 800000
#define DI 64
#define DH 256

// ---------------- scratch (device globals: no allocations allowed) ----------
__device__ float g_h[NN * DH];      // xs @ W_gcn
__device__ float g_xl[NN * DH];     // xs @ W_lin + b_lin
__device__ float g_z[NN * DH];      // tanh(aggregate + b_gcn)
__device__ int   g_deg[NN];         // in-degree (w/o self loop)
__device__ float g_dinv[NN];
__device__ int   g_rowptr[NN + 1];
__device__ int   g_fill[NN];
__device__ int   g_srcsorted[NE];
__device__ float g_colsum[DH];
__device__ float g_colsq[DH];
__device__ float g_scale[DH];
__device__ float g_shift[DH];
__device__ int   g_is64;

// ---------------- small kernels ---------------------------------------------
__global__ void init_kernel() {
    int i = blockIdx.x * blockDim.x + threadIdx.x;
    if (i < NN) { g_deg[i] = 0; g_fill[i] = 0; }
    if (i < DH) { g_colsum[i] = 0.f; g_colsq[i] = 0.f; }
}

// edge_index may be int64 or int32 depending on JAX x64 config.
// If the data is int32, interpreting as int64 combines two random values in
// [0,50000) -> astronomically unlikely that 64 consecutive int64 reads all
// land in [0, NN).
__global__ void detect_kernel(const void* ei) {
    if (threadIdx.x == 0 && blockIdx.x == 0) {
        const long long* p = (const long long*)ei;
        int ok = 1;
        for (int i = 0; i < 64; i++) {
            long long v = p[i];
            if (v < 0 || v >= NN) ok = 0;
        }
        g_is64 = ok;
    }
}

__device__ __forceinline__ int load_edge(const void* ei, int pos, int is64) {
    return is64 ? (int)((const long long*)ei)[pos] : ((const int*)ei)[pos];
}

__global__ void deg_kernel(const void* __restrict__ ei) {
    int e = blockIdx.x * blockDim.x + threadIdx.x;
    if (e >= NE) return;
    int d = load_edge(ei, NE + e, g_is64);
    atomicAdd(&g_deg[d], 1);
}

__global__ void dinv_kernel() {
    int i = blockIdx.x * blockDim.x + threadIdx.x;
    if (i < NN) g_dinv[i] = rsqrtf((float)(g_deg[i] + 1));  // +1 self loop
}

// single-block exclusive scan of g_deg -> g_rowptr
__global__ void scan_kernel() {
    __shared__ int s[1024];
    int t = threadIdx.x;
    const int C = (NN + 1023) / 1024;
    int start = t * C;
    int end = min(start + C, NN);
    int sum = 0;
    for (int i = start; i < end; i++) sum += g_deg[i];
    s[t] = sum;
    __syncthreads();
    for (int off = 1; off < 1024; off <<= 1) {
        int v = (t >= off) ? s[t - off] : 0;
        __syncthreads();
        s[t] += v;
        __syncthreads();
    }
    int run = s[t] - sum;  // exclusive prefix
    for (int i = start; i < end; i++) { g_rowptr[i] = run; run += g_deg[i]; }
    if (t == 0) g_rowptr[NN] = s[1023];
}

__global__ void scatter_kernel(const void* __restrict__ ei) {
    int e = blockIdx.x * blockDim.x + threadIdx.x;
    if (e >= NE) return;
    int is64 = g_is64;
    int d = load_edge(ei, NE + e, is64);
    int srcv = load_edge(ei, e, is64);
    int pos = g_rowptr[d] + atomicAdd(&g_fill[d], 1);
    g_srcsorted[pos] = srcv;
}

// ---------------- SIMT SGEMM 128x128 tile, 8x8 microtile --------------------
// C[M x 256] = A[M x KDIM] @ W[KDIM x 256]   (+ fused epilogues)
// EPI 0: C = acc              (h)
// EPI 1: C = acc + bias       (xl)
// EPI 2: gate fusion: g = sigmoid(acc + b_gate); out = relu((1-g)*xl + g*z)
//        + BN column-stat partial accumulation
template <int KDIM, int EPI>
__global__ __launch_bounds__(256, 2) void gemm_kernel(
    const float* __restrict__ A, const float* __restrict__ W,
    const float* __restrict__ bias, float* __restrict__ C)
{
    __shared__ float As[32][132];
    __shared__ float Ws[32][132];
    const int tid = threadIdx.x;
    const int tx = tid & 15;   // column group
    const int ty = tid >> 4;   // row group
    const int row0 = blockIdx.x * 128;
    const int col0 = blockIdx.y * 128;

    float acc[8][8];
#pragma unroll
    for (int i = 0; i < 8; i++)
#pragma unroll
        for (int j = 0; j < 8; j++) acc[i][j] = 0.f;

    for (int k0 = 0; k0 < KDIM; k0 += 32) {
        // load A tile (transposed into As[k][r])
#pragma unroll
        for (int it = 0; it < 4; it++) {
            int j = tid + it * 256;
            int r = j >> 3;
            int kq = (j & 7) * 4;
            float4 v = make_float4(0.f, 0.f, 0.f, 0.f);
            if (row0 + r < NN)
                v = *(const float4*)&A[(row0 + r) * KDIM + k0 + kq];
            As[kq + 0][r] = v.x;
            As[kq + 1][r] = v.y;
            As[kq + 2][r] = v.z;
            As[kq + 3][r] = v.w;
        }
        // load W tile
#pragma unroll
        for (int it = 0; it < 4; it++) {
            int j = tid + it * 256;
            int k = j >> 5;
            int cq = (j & 31) * 4;
            *(float4*)&Ws[k][cq] = *(const float4*)&W[(k0 + k) * DH + col0 + cq];
        }
        __syncthreads();
#pragma unroll
        for (int k = 0; k < 32; k++) {
            float4 a0 = *(const float4*)&As[k][ty * 4];
            float4 a1 = *(const float4*)&As[k][64 + ty * 4];
            float4 b0 = *(const float4*)&Ws[k][tx * 4];
            float4 b1 = *(const float4*)&Ws[k][64 + tx * 4];
            float a[8] = {a0.x, a0.y, a0.z, a0.w, a1.x, a1.y, a1.z, a1.w};
            float b[8] = {b0.x, b0.y, b0.z, b0.w, b1.x, b1.y, b1.z, b1.w};
#pragma unroll
            for (int i = 0; i < 8; i++)
#pragma unroll
                for (int j = 0; j < 8; j++) acc[i][j] += a[i] * b[j];
        }
        __syncthreads();
    }

    const int cA = col0 + tx * 4;
    const int cB = col0 + 64 + tx * 4;

    if (EPI == 0 || EPI == 1) {
        float4 bias0 = make_float4(0.f, 0.f, 0.f, 0.f);
        float4 bias1 = bias0;
        if (EPI == 1) {
            bias0 = *(const float4*)&bias[cA];
            bias1 = *(const float4*)&bias[cB];
        }
#pragma unroll
        for (int i = 0; i < 8; i++) {
            int row = row0 + ((i < 4) ? (ty * 4 + i) : (64 + ty * 4 + i - 4));
            if (row >= NN) continue;
            float4 o0 = make_float4(acc[i][0] + bias0.x, acc[i][1] + bias0.y,
                                    acc[i][2] + bias0.z, acc[i][3] + bias0.w);
            float4 o1 = make_float4(acc[i][4] + bias1.x, acc[i][5] + bias1.y,
                                    acc[i][6] + bias1.z, acc[i][7] + bias1.w);
            *(float4*)&C[row * DH + cA] = o0;
            *(float4*)&C[row * DH + cB] = o1;
        }
    } else {
        float4 bg0 = *(const float4*)&bias[cA];
        float4 bg1 = *(const float4*)&bias[cB];
        float ps[8], pq[8];
#pragma unroll
        for (int j = 0; j < 8; j++) { ps[j] = 0.f; pq[j] = 0.f; }
#pragma unroll
        for (int i = 0; i < 8; i++) {
            int row = row0 + ((i < 4) ? (ty * 4 + i) : (64 + ty * 4 + i - 4));
            if (row >= NN) continue;
            float4 xl0 = *(const float4*)&g_xl[row * DH + cA];
            float4 xl1 = *(const float4*)&g_xl[row * DH + cB];
            float4 z0 = *(const float4*)&g_z[row * DH + cA];
            float4 z1 = *(const float4*)&g_z[row * DH + cB];
            float o[8];
            const float* bgp0 = &bg0.x;
            const float* bgp1 = &bg1.x;
            const float* xlp0 = &xl0.x;
            const float* xlp1 = &xl1.x;
            const float* zp0 = &z0.x;
            const float* zp1 = &z1.x;
#pragma unroll
            for (int j = 0; j < 4; j++) {
                float gt = 1.f / (1.f + __expf(-(acc[i][j] + bgp0[j])));
                float v = fmaxf((1.f - gt) * xlp0[j] + gt * zp0[j], 0.f);
                o[j] = v;
                float gt1 = 1.f / (1.f + __expf(-(acc[i][j + 4] + bgp1[j])));
                float v1 = fmaxf((1.f - gt1) * xlp1[j] + gt1 * zp1[j], 0.f);
                o[j + 4] = v1;
            }
            *(float4*)&C[row * DH + cA] = make_float4(o[0], o[1], o[2], o[3]);
            *(float4*)&C[row * DH + cB] = make_float4(o[4], o[5], o[6], o[7]);
#pragma unroll
            for (int j = 0; j < 8; j++) { ps[j] += o[j]; pq[j] += o[j] * o[j]; }
        }
        // reduce with partner lane (same tx, other ty) then atomics
#pragma unroll
        for (int j = 0; j < 8; j++) {
            ps[j] += __shfl_xor_sync(0xffffffffu, ps[j], 16);
            pq[j] += __shfl_xor_sync(0xffffffffu, pq[j], 16);
        }
        if ((tid & 31) < 16) {
#pragma unroll
            for (int j = 0; j < 4; j++) {
                atomicAdd(&g_colsum[cA + j], ps[j]);
                atomicAdd(&g_colsq[cA + j], pq[j]);
                atomicAdd(&g_colsum[cB + j], ps[j + 4]);
                atomicAdd(&g_colsq[cB + j], pq[j + 4]);
            }
        }
    }
}

// ---------------- per-node aggregation (CSR, atomic-free) -------------------
__global__ void agg_kernel(const float* __restrict__ b_gcn) {
    int n = blockIdx.x;
    int t = threadIdx.x;  // 0..63, each owns 4 columns (float4)
    int beg = g_rowptr[n];
    int end = g_rowptr[n + 1];
    const float4* h4 = (const float4*)g_h;
    float4 acc = make_float4(0.f, 0.f, 0.f, 0.f);
    for (int k = beg; k < end; k++) {
        int s = g_srcsorted[k];
        float w = g_dinv[s];
        float4 hv = h4[s * (DH / 4) + t];
        acc.x += hv.x * w;
        acc.y += hv.y * w;
        acc.z += hv.z * w;
        acc.w += hv.w * w;
    }
    float di = g_dinv[n];
    float sw = di * di;
    float4 hs = h4[n * (DH / 4) + t];
    float4 b = ((const float4*)b_gcn)[t];
    float4 z;
    z.x = tanhf(acc.x * di + hs.x * sw + b.x);
    z.y = tanhf(acc.y * di + hs.y * sw + b.y);
    z.z = tanhf(acc.z * di + hs.z * sw + b.z);
    z.w = tanhf(acc.w * di + hs.w * sw + b.w);
    ((float4*)g_z)[n * (DH / 4) + t] = z;
}

// ---------------- batch-norm finalize ---------------------------------------
__global__ void bnstats_kernel(const float* __restrict__ gamma,
                               const float* __restrict__ beta) {
    int c = threadIdx.x;
    float mu = g_colsum[c] * (1.f / NN);
    float var = g_colsq[c] * (1.f / NN) - mu * mu;
    float rstd = rsqrtf(var + 1e-5f);
    float sc = rstd * gamma[c];
    g_scale[c] = sc;
    g_shift[c] = beta[c] - mu * sc;
}

__global__ void bnapply_kernel(float* __restrict__ out) {
    int i = blockIdx.x * blockDim.x + threadIdx.x;  // float4 index
    if (i >= NN * DH / 4) return;
    int c = (i & (DH / 4 - 1)) * 4;
    float4 v = ((float4*)out)[i];
    v.x = v.x * g_scale[c + 0] + g_shift[c + 0];
    v.y = v.y * g_scale[c + 1] + g_shift[c + 1];
    v.z = v.z * g_scale[c + 2] + g_shift[c + 2];
    v.w = v.w * g_scale[c + 3] + g_shift[c + 3];
    ((float4*)out)[i] = v;
}

// ---------------- launch -----------------------------------------------------
static float* sym_addr_f(const void* sym) {
    void* p = nullptr;
    cudaGetSymbolAddress(&p, sym);
    return (float*)p;
}

extern "C" void kernel_launch(void* const* d_in, const int* in_sizes, int n_in,
                              void* d_out, int out_size) {
    const float* xs     = (const float*)d_in[0];
    const void*  ei     = d_in[1];
    const float* W_gcn  = (const float*)d_in[2];
    const float* b_gcn  = (const float*)d_in[3];
    const float* W_lin  = (const float*)d_in[4];
    const float* b_lin  = (const float*)d_in[5];
    const float* W_gate = (const float*)d_in[6];
    const float* b_gate = (const float*)d_in[7];
    const float* gamma  = (const float*)d_in[8];
    const float* beta   = (const float*)d_in[9];
    float* out = (float*)d_out;

    float* p_h  = sym_addr_f(g_h);
    float* p_xl = sym_addr_f(g_xl);
    float* p_z  = sym_addr_f(g_z);

    init_kernel<<<(NN + 255) / 256, 256>>>();
    detect_kernel<<<1, 32>>>(ei);
    deg_kernel<<<(NE + 255) / 256, 256>>>(ei);
    dinv_kernel<<<(NN + 255) / 256, 256>>>();
    scan_kernel<<<1, 1024>>>();
    scatter_kernel<<<(NE + 255) / 256, 256>>>(ei);

    dim3 gg((NN + 127) / 128, DH / 128);
    gemm_kernel<DI, 0><<<gg, 256>>>(xs, W_gcn, nullptr, p_h);
    gemm_kernel<DI, 1><<<gg, 256>>>(xs, W_lin, b_lin, p_xl);

    agg_kernel<<<NN, 64>>>(b_gcn);

    gemm_kernel<DH, 2><<<gg, 256>>>(p_z, W_gate, b_gate, out);

    bnstats_kernel<<<1, DH>>>(gamma, beta);
    bnapply_kernel<<<(NN * DH / 4 + 255) / 256, 256>>>(out);
}

// round 6
// speedup vs baseline: 1.1800x; 1.1800x over previous
#include <cuda_runtime.h>
#include <math.h>

#define NN 50000
#define NE 800000
#define DI 64
#define DH 256

// ---------------- scratch (device globals: no allocations allowed) ----------
__device__ float g_h[NN * DH];      // xs @ W_gcn
__device__ float g_xl[NN * DH];     // xs @ W_lin + b_lin
__device__ float g_z[NN * DH];      // tanh(aggregate + b_gcn)
__device__ int   g_deg[NN];         // in-degree (w/o self loop)
__device__ float g_dinv[NN];
__device__ int   g_rowptr[NN + 1];
__device__ int   g_fill[NN];
__device__ int   g_srcsorted[NE];
__device__ float g_colsum[DH];
__device__ float g_colsq[DH];
__device__ float g_scale[DH];
__device__ float g_shift[DH];
__device__ int   g_is64;

// ---------------- small kernels ---------------------------------------------
__global__ void init_kernel() {
    int i = blockIdx.x * blockDim.x + threadIdx.x;
    if (i < NN) { g_deg[i] = 0; g_fill[i] = 0; }
    if (i < DH) { g_colsum[i] = 0.f; g_colsq[i] = 0.f; }
}

// edge_index may be int64 or int32 depending on JAX x64 config.
__global__ void detect_kernel(const void* ei) {
    if (threadIdx.x == 0 && blockIdx.x == 0) {
        const long long* p = (const long long*)ei;
        int ok = 1;
        for (int i = 0; i < 64; i++) {
            long long v = p[i];
            if (v < 0 || v >= NN) ok = 0;
        }
        g_is64 = ok;
    }
}

__device__ __forceinline__ int load_edge(const void* ei, int pos, int is64) {
    return is64 ? (int)((const long long*)ei)[pos] : ((const int*)ei)[pos];
}

__global__ void deg_kernel(const void* __restrict__ ei) {
    int e = blockIdx.x * blockDim.x + threadIdx.x;
    if (e >= NE) return;
    int d = load_edge(ei, NE + e, g_is64);
    atomicAdd(&g_deg[d], 1);
}

__global__ void dinv_kernel() {
    int i = blockIdx.x * blockDim.x + threadIdx.x;
    if (i < NN) g_dinv[i] = rsqrtf((float)(g_deg[i] + 1));  // +1 self loop
}

// single-block exclusive scan of g_deg -> g_rowptr
__global__ void scan_kernel() {
    __shared__ int s[1024];
    int t = threadIdx.x;
    const int C = (NN + 1023) / 1024;
    int start = t * C;
    int end = min(start + C, NN);
    int sum = 0;
    for (int i = start; i < end; i++) sum += g_deg[i];
    s[t] = sum;
    __syncthreads();
    for (int off = 1; off < 1024; off <<= 1) {
        int v = (t >= off) ? s[t - off] : 0;
        __syncthreads();
        s[t] += v;
        __syncthreads();
    }
    int run = s[t] - sum;  // exclusive prefix
    for (int i = start; i < end; i++) { g_rowptr[i] = run; run += g_deg[i]; }
    if (t == 0) g_rowptr[NN] = s[1023];
}

__global__ void scatter_kernel(const void* __restrict__ ei) {
    int e = blockIdx.x * blockDim.x + threadIdx.x;
    if (e >= NE) return;
    int is64 = g_is64;
    int d = load_edge(ei, NE + e, is64);
    int srcv = load_edge(ei, e, is64);
    int pos = g_rowptr[d] + atomicAdd(&g_fill[d], 1);
    g_srcsorted[pos] = srcv;
}

// ---------------- tf32 tensor-core GEMM (split-3 for fp32 precision) --------
// C[M x 256] = A[M x KDIM] @ W[KDIM x 256]   (+ fused epilogues)
// EPI 0: C = acc              (h)
// EPI 1: C = acc + bias       (xl)
// EPI 2: g = sigmoid(acc + b_gate); C = relu((1-g)*xl + g*z)

__device__ __forceinline__ void split_tf32(float x, unsigned& hi, unsigned& lo) {
    unsigned h;
    asm("cvt.rna.tf32.f32 %0, %1;" : "=r"(h) : "f"(x));
    float r = x - __uint_as_float(h);
    unsigned l;
    asm("cvt.rna.tf32.f32 %0, %1;" : "=r"(l) : "f"(r));
    hi = h; lo = l;
}

__device__ __forceinline__ void mma_tf32(float c[4], const unsigned a[4],
                                         unsigned b0, unsigned b1) {
    asm volatile(
        "mma.sync.aligned.m16n8k8.row.col.f32.tf32.tf32.f32 "
        "{%0,%1,%2,%3},{%4,%5,%6,%7},{%8,%9},{%0,%1,%2,%3};\n"
        : "+f"(c[0]), "+f"(c[1]), "+f"(c[2]), "+f"(c[3])
        : "r"(a[0]), "r"(a[1]), "r"(a[2]), "r"(a[3]), "r"(b0), "r"(b1));
}

template <int KDIM, int EPI>
__global__ __launch_bounds__(256) void gemm_tc(
    const float* __restrict__ A, const float* __restrict__ W,
    const float* __restrict__ bias, float* __restrict__ C)
{
    __shared__ float As[32][132];   // [k][row]
    __shared__ float Ws[32][132];   // [k][col]
    const int tid = threadIdx.x;
    const int lane = tid & 31;
    const int wid = tid >> 5;
    const int wr = wid & 3;         // warp row (0..3) -> 32 rows each
    const int wc = wid >> 2;        // warp col (0..1) -> 64 cols each
    const int lq = lane & 3;        // k offset inside fragment
    const int lg = lane >> 2;       // row/col group inside fragment
    const int row0 = blockIdx.x * 128;
    const int col0 = blockIdx.y * 128;

    float acc[2][8][4];
#pragma unroll
    for (int mt = 0; mt < 2; mt++)
#pragma unroll
        for (int nt = 0; nt < 8; nt++)
#pragma unroll
            for (int j = 0; j < 4; j++) acc[mt][nt][j] = 0.f;

    for (int k0 = 0; k0 < KDIM; k0 += 32) {
        // load A tile (transposed into As[k][r])
#pragma unroll
        for (int it = 0; it < 4; it++) {
            int j = tid + it * 256;
            int r = j >> 3;
            int kq = (j & 7) * 4;
            float4 v = make_float4(0.f, 0.f, 0.f, 0.f);
            if (row0 + r < NN)
                v = *(const float4*)&A[(row0 + r) * KDIM + k0 + kq];
            As[kq + 0][r] = v.x;
            As[kq + 1][r] = v.y;
            As[kq + 2][r] = v.z;
            As[kq + 3][r] = v.w;
        }
        // load W tile
#pragma unroll
        for (int it = 0; it < 4; it++) {
            int j = tid + it * 256;
            int k = j >> 5;
            int cq = (j & 31) * 4;
            *(float4*)&Ws[k][cq] = *(const float4*)&W[(k0 + k) * DH + col0 + cq];
        }
        __syncthreads();

#pragma unroll
        for (int ks = 0; ks < 4; ks++) {
            const int kb = ks * 8;
            unsigned ah[2][4], al[2][4];
#pragma unroll
            for (int mt = 0; mt < 2; mt++) {
                int rb = wr * 32 + mt * 16 + lg;
                float x0 = As[kb + lq][rb];
                float x1 = As[kb + lq][rb + 8];
                float x2 = As[kb + lq + 4][rb];
                float x3 = As[kb + lq + 4][rb + 8];
                split_tf32(x0, ah[mt][0], al[mt][0]);
                split_tf32(x1, ah[mt][1], al[mt][1]);
                split_tf32(x2, ah[mt][2], al[mt][2]);
                split_tf32(x3, ah[mt][3], al[mt][3]);
            }
#pragma unroll
            for (int nt = 0; nt < 8; nt++) {
                int cb = wc * 64 + nt * 8 + lg;
                float y0 = Ws[kb + lq][cb];
                float y1 = Ws[kb + lq + 4][cb];
                unsigned bh0, bl0, bh1, bl1;
                split_tf32(y0, bh0, bl0);
                split_tf32(y1, bh1, bl1);
#pragma unroll
                for (int mt = 0; mt < 2; mt++) {
                    mma_tf32(acc[mt][nt], ah[mt], bh0, bh1);  // hi*hi
                    mma_tf32(acc[mt][nt], al[mt], bh0, bh1);  // lo*hi
                    mma_tf32(acc[mt][nt], ah[mt], bl0, bl1);  // hi*lo
                }
            }
        }
        __syncthreads();
    }

    // ---------------- epilogue ----------------
#pragma unroll
    for (int mt = 0; mt < 2; mt++) {
        int r = row0 + wr * 32 + mt * 16 + lg;     // rows r and r+8
#pragma unroll
        for (int nt = 0; nt < 8; nt++) {
            int c = col0 + wc * 64 + nt * 8 + 2 * lq;
            float* a = acc[mt][nt];
            if (EPI == 0) {
                if (r < NN)     *(float2*)&C[r * DH + c]       = make_float2(a[0], a[1]);
                if (r + 8 < NN) *(float2*)&C[(r + 8) * DH + c] = make_float2(a[2], a[3]);
            } else if (EPI == 1) {
                float2 bb = *(const float2*)&bias[c];
                if (r < NN)
                    *(float2*)&C[r * DH + c] = make_float2(a[0] + bb.x, a[1] + bb.y);
                if (r + 8 < NN)
                    *(float2*)&C[(r + 8) * DH + c] = make_float2(a[2] + bb.x, a[3] + bb.y);
            } else {
                float2 bg = *(const float2*)&bias[c];
#pragma unroll
                for (int half = 0; half < 2; half++) {
                    int row = r + half * 8;
                    if (row >= NN) continue;
                    float2 xl = *(const float2*)&g_xl[row * DH + c];
                    float2 zz = *(const float2*)&g_z[row * DH + c];
                    float g0 = 1.f / (1.f + __expf(-(a[half * 2 + 0] + bg.x)));
                    float g1 = 1.f / (1.f + __expf(-(a[half * 2 + 1] + bg.y)));
                    float o0 = fmaxf((1.f - g0) * xl.x + g0 * zz.x, 0.f);
                    float o1 = fmaxf((1.f - g1) * xl.y + g1 * zz.y, 0.f);
                    *(float2*)&C[row * DH + c] = make_float2(o0, o1);
                }
            }
        }
    }
}

// ---------------- per-node aggregation (CSR, atomic-free) -------------------
__global__ void agg_kernel(const float* __restrict__ b_gcn) {
    int n = blockIdx.x;
    int t = threadIdx.x;  // 0..63, each owns 4 columns (float4)
    int beg = g_rowptr[n];
    int end = g_rowptr[n + 1];
    const float4* h4 = (const float4*)g_h;
    float4 acc = make_float4(0.f, 0.f, 0.f, 0.f);
    for (int k = beg; k < end; k++) {
        int s = g_srcsorted[k];
        float w = g_dinv[s];
        float4 hv = h4[s * (DH / 4) + t];
        acc.x += hv.x * w;
        acc.y += hv.y * w;
        acc.z += hv.z * w;
        acc.w += hv.w * w;
    }
    float di = g_dinv[n];
    float sw = di * di;
    float4 hs = h4[n * (DH / 4) + t];
    float4 b = ((const float4*)b_gcn)[t];
    float4 z;
    z.x = tanhf(acc.x * di + hs.x * sw + b.x);
    z.y = tanhf(acc.y * di + hs.y * sw + b.y);
    z.z = tanhf(acc.z * di + hs.z * sw + b.z);
    z.w = tanhf(acc.w * di + hs.w * sw + b.w);
    ((float4*)g_z)[n * (DH / 4) + t] = z;
}

// ---------------- batch-norm -------------------------------------------------
__global__ void bnreduce_kernel(const float* __restrict__ out) {
    int c = threadIdx.x;            // 256 threads = 256 columns
    int r0 = blockIdx.x * 128;
    int rend = min(r0 + 128, NN);
    float s = 0.f, q = 0.f;
    for (int r = r0; r < rend; r++) {
        float v = out[r * DH + c];
        s += v;
        q += v * v;
    }
    atomicAdd(&g_colsum[c], s);
    atomicAdd(&g_colsq[c], q);
}

__global__ void bnstats_kernel(const float* __restrict__ gamma,
                               const float* __restrict__ beta) {
    int c = threadIdx.x;
    float mu = g_colsum[c] * (1.f / NN);
    float var = g_colsq[c] * (1.f / NN) - mu * mu;
    float rstd = rsqrtf(var + 1e-5f);
    float sc = rstd * gamma[c];
    g_scale[c] = sc;
    g_shift[c] = beta[c] - mu * sc;
}

__global__ void bnapply_kernel(float* __restrict__ out) {
    int i = blockIdx.x * blockDim.x + threadIdx.x;  // float4 index
    if (i >= NN * DH / 4) return;
    int c = (i & (DH / 4 - 1)) * 4;
    float4 v = ((float4*)out)[i];
    v.x = v.x * g_scale[c + 0] + g_shift[c + 0];
    v.y = v.y * g_scale[c + 1] + g_shift[c + 1];
    v.z = v.z * g_scale[c + 2] + g_shift[c + 2];
    v.w = v.w * g_scale[c + 3] + g_shift[c + 3];
    ((float4*)out)[i] = v;
}

// ---------------- launch -----------------------------------------------------
static float* sym_addr_f(const void* sym) {
    void* p = nullptr;
    cudaGetSymbolAddress(&p, sym);
    return (float*)p;
}

extern "C" void kernel_launch(void* const* d_in, const int* in_sizes, int n_in,
                              void* d_out, int out_size) {
    const float* xs     = (const float*)d_in[0];
    const void*  ei     = d_in[1];
    const float* W_gcn  = (const float*)d_in[2];
    const float* b_gcn  = (const float*)d_in[3];
    const float* W_lin  = (const float*)d_in[4];
    const float* b_lin  = (const float*)d_in[5];
    const float* W_gate = (const float*)d_in[6];
    const float* b_gate = (const float*)d_in[7];
    const float* gamma  = (const float*)d_in[8];
    const float* beta   = (const float*)d_in[9];
    float* out = (float*)d_out;

    float* p_h  = sym_addr_f(g_h);
    float* p_xl = sym_addr_f(g_xl);
    float* p_z  = sym_addr_f(g_z);

    init_kernel<<<(NN + 255) / 256, 256>>>();
    detect_kernel<<<1, 32>>>(ei);
    deg_kernel<<<(NE + 255) / 256, 256>>>(ei);
    dinv_kernel<<<(NN + 255) / 256, 256>>>();
    scan_kernel<<<1, 1024>>>();
    scatter_kernel<<<(NE + 255) / 256, 256>>>(ei);

    dim3 gg((NN + 127) / 128, DH / 128);
    gemm_tc<DI, 0><<<gg, 256>>>(xs, W_gcn, nullptr, p_h);
    gemm_tc<DI, 1><<<gg, 256>>>(xs, W_lin, b_lin, p_xl);

    agg_kernel<<<NN, 64>>>(b_gcn);

    gemm_tc<DH, 2><<<gg, 256>>>(p_z, W_gate, b_gate, out);

    bnreduce_kernel<<<(NN + 127) / 128, 256>>>(out);
    bnstats_kernel<<<1, DH>>>(gamma, beta);
    bnapply_kernel<<<(NN * DH / 4 + 255) / 256, 256>>>(out);
}

// round 10
// speedup vs baseline: 1.4210x; 1.2042x over previous
#include <cuda_runtime.h>
#include <cuda_bf16.h>
#include <math.h>

#define NN 50000
#define NE 800000
#define DI 64
#define DH 256

// ---------------- scratch (device globals) -----------------------------------
__device__ float g_xl[NN * DH];     // xs @ W_lin + b_lin
__device__ float g_z[NN * DH];      // tanh(xagg @ W_gcn + b_gcn)
__device__ __align__(16) __nv_bfloat16 g_xsh[NN * DI];   // xs hi  [row][k]
__device__ __align__(16) __nv_bfloat16 g_xsl[NN * DI];   // xs lo
__device__ __align__(16) __nv_bfloat16 g_xah[NN * DI];   // xagg hi [row][k]
__device__ __align__(16) __nv_bfloat16 g_xal[NN * DI];
__device__ __align__(16) __nv_bfloat16 g_zh[NN * DH];    // z hi [row][k]
__device__ __align__(16) __nv_bfloat16 g_zl[NN * DH];
__device__ __align__(16) __nv_bfloat16 g_wch[DH * DI];   // W_gcn  [col][k]
__device__ __align__(16) __nv_bfloat16 g_wcl[DH * DI];
__device__ __align__(16) __nv_bfloat16 g_wlh[DH * DI];   // W_lin  [col][k]
__device__ __align__(16) __nv_bfloat16 g_wll[DH * DI];
__device__ __align__(16) __nv_bfloat16 g_wgh[DH * DH];   // W_gate [col][k]
__device__ __align__(16) __nv_bfloat16 g_wgl[DH * DH];
__device__ int   g_deg[NN];
__device__ float g_dinv[NN];
__device__ int   g_rowptr[NN + 1];
__device__ int   g_fill[NN];
__device__ int   g_srcsorted[NE];
__device__ float g_colsum[DH];
__device__ float g_colsq[DH];
__device__ float g_scale[DH];
__device__ float g_shift[DH];
__device__ int   g_is64;

__device__ __forceinline__ void bsplit(float x, __nv_bfloat16& h, __nv_bfloat16& l) {
    h = __float2bfloat16(x);
    l = __float2bfloat16(x - __bfloat162float(h));
}

// ---------------- small kernels ----------------------------------------------
__global__ void init_kernel() {
    int i = blockIdx.x * blockDim.x + threadIdx.x;
    if (i < NN) { g_deg[i] = 0; g_fill[i] = 0; }
    if (i < DH) { g_colsum[i] = 0.f; g_colsq[i] = 0.f; }
}

__global__ void detect_kernel(const void* ei) {
    if (threadIdx.x == 0 && blockIdx.x == 0) {
        const long long* p = (const long long*)ei;
        int ok = 1;
        for (int i = 0; i < 64; i++) {
            long long v = p[i];
            if (v < 0 || v >= NN) ok = 0;
        }
        g_is64 = ok;
    }
}

__device__ __forceinline__ int load_edge(const void* ei, int pos, int is64) {
    return is64 ? (int)((const long long*)ei)[pos] : ((const int*)ei)[pos];
}

__global__ void deg_kernel(const void* __restrict__ ei) {
    int e = blockIdx.x * blockDim.x + threadIdx.x;
    if (e >= NE) return;
    int d = load_edge(ei, NE + e, g_is64);
    atomicAdd(&g_deg[d], 1);
}

__global__ void dinv_kernel() {
    int i = blockIdx.x * blockDim.x + threadIdx.x;
    if (i < NN) g_dinv[i] = rsqrtf((float)(g_deg[i] + 1));
}

__global__ void scan_kernel() {
    __shared__ int s[1024];
    int t = threadIdx.x;
    const int C = (NN + 1023) / 1024;
    int start = t * C;
    int end = min(start + C, NN);
    int sum = 0;
    for (int i = start; i < end; i++) sum += g_deg[i];
    s[t] = sum;
    __syncthreads();
    for (int off = 1; off < 1024; off <<= 1) {
        int v = (t >= off) ? s[t - off] : 0;
        __syncthreads();
        s[t] += v;
        __syncthreads();
    }
    int run = s[t] - sum;
    for (int i = start; i < end; i++) { g_rowptr[i] = run; run += g_deg[i]; }
    if (t == 0) g_rowptr[NN] = s[1023];
}

__global__ void scatter_kernel(const void* __restrict__ ei) {
    int e = blockIdx.x * blockDim.x + threadIdx.x;
    if (e >= NE) return;
    int is64 = g_is64;
    int d = load_edge(ei, NE + e, is64);
    int srcv = load_edge(ei, e, is64);
    int pos = g_rowptr[d] + atomicAdd(&g_fill[d], 1);
    g_srcsorted[pos] = srcv;
}

// ---------------- weight / input pre-splitting -------------------------------
// weights transposed to [col][k] bf16 hi/lo
__global__ void wsplit_kernel(const float* __restrict__ Wc,
                              const float* __restrict__ Wl,
                              const float* __restrict__ Wg) {
    int i = blockIdx.x * blockDim.x + threadIdx.x;
    const int NW1 = DH * DI;                 // 16384 per small weight
    if (i < 2 * NW1) {
        int sel = i / NW1;
        int j = i - sel * NW1;
        int c = j / DI, k = j - c * DI;
        float x = (sel ? Wl : Wc)[k * DH + c];
        __nv_bfloat16 h, l;
        bsplit(x, h, l);
        if (sel) { g_wlh[j] = h; g_wll[j] = l; }
        else     { g_wch[j] = h; g_wcl[j] = l; }
    } else {
        int j = i - 2 * NW1;
        if (j >= DH * DH) return;
        int c = j / DH, k = j - c * DH;
        float x = Wg[k * DH + c];
        __nv_bfloat16 h, l;
        bsplit(x, h, l);
        g_wgh[j] = h; g_wgl[j] = l;
    }
}

__global__ void xsplit_kernel(const float* __restrict__ xs) {
    int i = blockIdx.x * blockDim.x + threadIdx.x;  // float4 index
    if (i >= NN * DI / 4) return;
    float4 v = ((const float4*)xs)[i];
    __nv_bfloat162 h0, l0, h1, l1;
    bsplit(v.x, h0.x, l0.x); bsplit(v.y, h0.y, l0.y);
    bsplit(v.z, h1.x, l1.x); bsplit(v.w, h1.y, l1.y);
    ((__nv_bfloat162*)g_xsh)[i * 2] = h0;
    ((__nv_bfloat162*)g_xsh)[i * 2 + 1] = h1;
    ((__nv_bfloat162*)g_xsl)[i * 2] = l0;
    ((__nv_bfloat162*)g_xsl)[i * 2 + 1] = l1;
}

// ---------------- 64-dim aggregation (warp per node, CSR) --------------------
// xagg[n] = dinv[n] * sum_{src->n} dinv[src]*xs[src] + dinv[n]^2 * xs[n]
__global__ __launch_bounds__(256) void aggx_kernel(const float* __restrict__ xs) {
    int w = (blockIdx.x * 256 + threadIdx.x) >> 5;
    int lane = threadIdx.x & 31;
    if (w >= NN) return;
    int beg = g_rowptr[w];
    int end = g_rowptr[w + 1];
    const float2* xs2 = (const float2*)xs;
    float2 acc = make_float2(0.f, 0.f);
    for (int k = beg; k < end; k++) {
        int s = g_srcsorted[k];
        float wt = g_dinv[s];
        float2 v = xs2[s * 32 + lane];
        acc.x += v.x * wt;
        acc.y += v.y * wt;
    }
    float di = g_dinv[w];
    float2 xv = xs2[w * 32 + lane];
    float rx = acc.x * di + xv.x * di * di;
    float ry = acc.y * di + xv.y * di * di;
    __nv_bfloat162 h2, l2;
    bsplit(rx, h2.x, l2.x);
    bsplit(ry, h2.y, l2.y);
    ((__nv_bfloat162*)g_xah)[w * 32 + lane] = h2;
    ((__nv_bfloat162*)g_xal)[w * 32 + lane] = l2;
}

// ---------------- bf16 split-3 tensor-core GEMM ------------------------------
// C[M x 256] = A[M x KDIM] @ W[KDIM x 256]
// A pre-split bf16 hi/lo [row][KDIM]; W pre-split bf16 [col][KDIM].
// EPI 0: z = tanh(acc + b_gcn) -> g_z fp32 + g_zh/g_zl bf16 split
// EPI 1: C = acc + bias
// EPI 2: g = sigmoid(acc + b_gate); C = relu((1-g)*xl + g*z)

__device__ __forceinline__ void mma_bf16(float c[4], const unsigned a[4],
                                         unsigned b0, unsigned b1) {
    asm volatile(
        "mma.sync.aligned.m16n8k16.row.col.f32.bf16.bf16.f32 "
        "{%0,%1,%2,%3},{%4,%5,%6,%7},{%8,%9},{%0,%1,%2,%3};\n"
        : "+f"(c[0]), "+f"(c[1]), "+f"(c[2]), "+f"(c[3])
        : "r"(a[0]), "r"(a[1]), "r"(a[2]), "r"(a[3]), "r"(b0), "r"(b1));
}

#define SSTR 40   // smem row stride in bf16 elems

template <int KDIM, int EPI>
__global__ __launch_bounds__(256) void gemm_bf(
    const __nv_bfloat16* __restrict__ Ahg, const __nv_bfloat16* __restrict__ Alg,
    const __nv_bfloat16* __restrict__ Whg, const __nv_bfloat16* __restrict__ Wlg,
    const float* __restrict__ bias, float* __restrict__ C)
{
    __shared__ __align__(16) __nv_bfloat16 Ash[2][128 * SSTR];
    __shared__ __align__(16) __nv_bfloat16 Wsh[2][128 * SSTR];
    const int tid = threadIdx.x;
    const int lane = tid & 31;
    const int wid = tid >> 5;
    const int wr = wid & 3;         // warp row (0..3) -> 32 rows
    const int wcq = wid >> 2;       // warp col (0..1) -> 64 cols
    const int lq = lane & 3;
    const int lg = lane >> 2;
    const int row0 = blockIdx.x * 128;
    const int col0 = blockIdx.y * 128;

    float acc[2][8][4];
#pragma unroll
    for (int mt = 0; mt < 2; mt++)
#pragma unroll
        for (int nt = 0; nt < 8; nt++)
#pragma unroll
            for (int j = 0; j < 4; j++) acc[mt][nt][j] = 0.f;

    const int lr = tid >> 1;            // 0..127: tile row (A) / col (W)
    const int hf = (tid & 1) * 16;      // 16-elem half of the 32-k slab

    for (int k0 = 0; k0 < KDIM; k0 += 32) {
        // A tile copy: each thread covers 16 bf16 = 2x uint4 per plane
        uint4 vh0 = make_uint4(0u,0u,0u,0u), vh1 = vh0, vl0 = vh0, vl1 = vh0;
        long grow = row0 + lr;
        if (grow < NN) {
            const __nv_bfloat16* pa = &Ahg[grow * KDIM + k0 + hf];
            const __nv_bfloat16* pl = &Alg[grow * KDIM + k0 + hf];
            vh0 = *(const uint4*)pa;
            vh1 = *(const uint4*)(pa + 8);
            vl0 = *(const uint4*)pl;
            vl1 = *(const uint4*)(pl + 8);
        }
        *(uint4*)&Ash[0][lr * SSTR + hf]     = vh0;
        *(uint4*)&Ash[0][lr * SSTR + hf + 8] = vh1;
        *(uint4*)&Ash[1][lr * SSTR + hf]     = vl0;
        *(uint4*)&Ash[1][lr * SSTR + hf + 8] = vl1;
        // W tile copy (cols always in-bounds: 256 total)
        {
            long gcol = col0 + lr;
            const __nv_bfloat16* pw = &Whg[gcol * KDIM + k0 + hf];
            const __nv_bfloat16* pq = &Wlg[gcol * KDIM + k0 + hf];
            *(uint4*)&Wsh[0][lr * SSTR + hf]     = *(const uint4*)pw;
            *(uint4*)&Wsh[0][lr * SSTR + hf + 8] = *(const uint4*)(pw + 8);
            *(uint4*)&Wsh[1][lr * SSTR + hf]     = *(const uint4*)pq;
            *(uint4*)&Wsh[1][lr * SSTR + hf + 8] = *(const uint4*)(pq + 8);
        }
        __syncthreads();

#pragma unroll
        for (int ks = 0; ks < 2; ks++) {
            const int kb = ks * 16;
            unsigned ah[2][4], al[2][4];
#pragma unroll
            for (int mt = 0; mt < 2; mt++) {
                int rb = wr * 32 + mt * 16 + lg;
                ah[mt][0] = *(const unsigned*)&Ash[0][rb * SSTR + kb + 2 * lq];
                ah[mt][1] = *(const unsigned*)&Ash[0][(rb + 8) * SSTR + kb + 2 * lq];
                ah[mt][2] = *(const unsigned*)&Ash[0][rb * SSTR + kb + 8 + 2 * lq];
                ah[mt][3] = *(const unsigned*)&Ash[0][(rb + 8) * SSTR + kb + 8 + 2 * lq];
                al[mt][0] = *(const unsigned*)&Ash[1][rb * SSTR + kb + 2 * lq];
                al[mt][1] = *(const unsigned*)&Ash[1][(rb + 8) * SSTR + kb + 2 * lq];
                al[mt][2] = *(const unsigned*)&Ash[1][rb * SSTR + kb + 8 + 2 * lq];
                al[mt][3] = *(const unsigned*)&Ash[1][(rb + 8) * SSTR + kb + 8 + 2 * lq];
            }
#pragma unroll
            for (int nt = 0; nt < 8; nt++) {
                int cb = wcq * 64 + nt * 8 + lg;
                unsigned bh0 = *(const unsigned*)&Wsh[0][cb * SSTR + kb + 2 * lq];
                unsigned bh1 = *(const unsigned*)&Wsh[0][cb * SSTR + kb + 8 + 2 * lq];
                unsigned bl0 = *(const unsigned*)&Wsh[1][cb * SSTR + kb + 2 * lq];
                unsigned bl1 = *(const unsigned*)&Wsh[1][cb * SSTR + kb + 8 + 2 * lq];
#pragma unroll
                for (int mt = 0; mt < 2; mt++) {
                    mma_bf16(acc[mt][nt], ah[mt], bh0, bh1);  // hi*hi
                    mma_bf16(acc[mt][nt], al[mt], bh0, bh1);  // lo*hi
                    mma_bf16(acc[mt][nt], ah[mt], bl0, bl1);  // hi*lo
                }
            }
        }
        __syncthreads();
    }

    // ---------------- epilogue ----------------
#pragma unroll
    for (int mt = 0; mt < 2; mt++) {
        int r = row0 + wr * 32 + mt * 16 + lg;  // rows r, r+8
#pragma unroll
        for (int nt = 0; nt < 8; nt++) {
            int c = col0 + wcq * 64 + nt * 8 + 2 * lq;
            float* a = acc[mt][nt];
            float2 bb = *(const float2*)&bias[c];
            if (EPI == 0) {
#pragma unroll
                for (int half = 0; half < 2; half++) {
                    int row = r + half * 8;
                    if (row >= NN) continue;
                    float z0 = tanhf(a[half * 2 + 0] + bb.x);
                    float z1 = tanhf(a[half * 2 + 1] + bb.y);
                    *(float2*)&C[row * DH + c] = make_float2(z0, z1);
                    __nv_bfloat162 h2, l2;
                    bsplit(z0, h2.x, l2.x);
                    bsplit(z1, h2.y, l2.y);
                    ((__nv_bfloat162*)g_zh)[(row * DH + c) >> 1] = h2;
                    ((__nv_bfloat162*)g_zl)[(row * DH + c) >> 1] = l2;
                }
            } else if (EPI == 1) {
                if (r < NN)
                    *(float2*)&C[r * DH + c] = make_float2(a[0] + bb.x, a[1] + bb.y);
                if (r + 8 < NN)
                    *(float2*)&C[(r + 8) * DH + c] = make_float2(a[2] + bb.x, a[3] + bb.y);
            } else {
#pragma unroll
                for (int half = 0; half < 2; half++) {
                    int row = r + half * 8;
                    if (row >= NN) continue;
                    float2 xl = *(const float2*)&g_xl[row * DH + c];
                    float2 zz = *(const float2*)&g_z[row * DH + c];
                    float g0 = 1.f / (1.f + __expf(-(a[half * 2 + 0] + bb.x)));
                    float g1 = 1.f / (1.f + __expf(-(a[half * 2 + 1] + bb.y)));
                    float o0 = fmaxf((1.f - g0) * xl.x + g0 * zz.x, 0.f);
                    float o1 = fmaxf((1.f - g1) * xl.y + g1 * zz.y, 0.f);
                    *(float2*)&C[row * DH + c] = make_float2(o0, o1);
                }
            }
        }
    }
}

// ---------------- batch-norm -------------------------------------------------
__global__ void bnreduce_kernel(const float* __restrict__ out) {
    int c = threadIdx.x;
    int r0 = blockIdx.x * 128;
    int rend = min(r0 + 128, NN);
    float s = 0.f, q = 0.f;
    for (int r = r0; r < rend; r++) {
        float v = out[r * DH + c];
        s += v;
        q += v * v;
    }
    atomicAdd(&g_colsum[c], s);
    atomicAdd(&g_colsq[c], q);
}

__global__ void bnstats_kernel(const float* __restrict__ gamma,
                               const float* __restrict__ beta) {
    int c = threadIdx.x;
    float mu = g_colsum[c] * (1.f / NN);
    float var = g_colsq[c] * (1.f / NN) - mu * mu;
    float rstd = rsqrtf(var + 1e-5f);
    float sc = rstd * gamma[c];
    g_scale[c] = sc;
    g_shift[c] = beta[c] - mu * sc;
}

__global__ void bnapply_kernel(float* __restrict__ out) {
    int i = blockIdx.x * blockDim.x + threadIdx.x;
    if (i >= NN * DH / 4) return;
    int c = (i & (DH / 4 - 1)) * 4;
    float4 v = ((float4*)out)[i];
    v.x = v.x * g_scale[c + 0] + g_shift[c + 0];
    v.y = v.y * g_scale[c + 1] + g_shift[c + 1];
    v.z = v.z * g_scale[c + 2] + g_shift[c + 2];
    v.w = v.w * g_scale[c + 3] + g_shift[c + 3];
    ((float4*)out)[i] = v;
}

// ---------------- launch -----------------------------------------------------
template <typename T>
static T* symp(const void* sym) {
    void* p = nullptr;
    cudaGetSymbolAddress(&p, sym);
    return (T*)p;
}

extern "C" void kernel_launch(void* const* d_in, const int* in_sizes, int n_in,
                              void* d_out, int out_size) {
    const float* xs     = (const float*)d_in[0];
    const void*  ei     = d_in[1];
    const float* W_gcn  = (const float*)d_in[2];
    const float* b_gcn  = (const float*)d_in[3];
    const float* W_lin  = (const float*)d_in[4];
    const float* b_lin  = (const float*)d_in[5];
    const float* W_gate = (const float*)d_in[6];
    const float* b_gate = (const float*)d_in[7];
    const float* gamma  = (const float*)d_in[8];
    const float* beta   = (const float*)d_in[9];
    float* out = (float*)d_out;

    float* p_xl = symp<float>(g_xl);
    float* p_z  = symp<float>(g_z);
    __nv_bfloat16* p_xsh = symp<__nv_bfloat16>(g_xsh);
    __nv_bfloat16* p_xsl = symp<__nv_bfloat16>(g_xsl);
    __nv_bfloat16* p_xah = symp<__nv_bfloat16>(g_xah);
    __nv_bfloat16* p_xal = symp<__nv_bfloat16>(g_xal);
    __nv_bfloat16* p_zh  = symp<__nv_bfloat16>(g_zh);
    __nv_bfloat16* p_zl  = symp<__nv_bfloat16>(g_zl);
    __nv_bfloat16* p_wch = symp<__nv_bfloat16>(g_wch);
    __nv_bfloat16* p_wcl = symp<__nv_bfloat16>(g_wcl);
    __nv_bfloat16* p_wlh = symp<__nv_bfloat16>(g_wlh);
    __nv_bfloat16* p_wll = symp<__nv_bfloat16>(g_wll);
    __nv_bfloat16* p_wgh = symp<__nv_bfloat16>(g_wgh);
    __nv_bfloat16* p_wgl = symp<__nv_bfloat16>(g_wgl);

    init_kernel<<<(NN + 255) / 256, 256>>>();
    detect_kernel<<<1, 32>>>(ei);
    deg_kernel<<<(NE + 255) / 256, 256>>>(ei);
    dinv_kernel<<<(NN + 255) / 256, 256>>>();
    scan_kernel<<<1, 1024>>>();
    scatter_kernel<<<(NE + 255) / 256, 256>>>(ei);

    wsplit_kernel<<<(2 * DH * DI + DH * DH + 255) / 256, 256>>>(W_gcn, W_lin, W_gate);
    xsplit_kernel<<<(NN * DI / 4 + 255) / 256, 256>>>(xs);

    aggx_kernel<<<(NN + 7) / 8, 256>>>(xs);

    dim3 gg((NN + 127) / 128, 2);
    gemm_bf<DI, 0><<<gg, 256>>>(p_xah, p_xal, p_wch, p_wcl, b_gcn, p_z);
    gemm_bf<DI, 1><<<gg, 256>>>(p_xsh, p_xsl, p_wlh, p_wll, b_lin, p_xl);
    gemm_bf<DH, 2><<<gg, 256>>>(p_zh, p_zl, p_wgh, p_wgl, b_gate, out);

    bnreduce_kernel<<<(NN + 127) / 128, 256>>>(out);
    bnstats_kernel<<<1, DH>>>(gamma, beta);
    bnapply_kernel<<<(NN * DH / 4 + 255) / 256, 256>>>(out);
}